// round 2
// baseline (speedup 1.0000x reference)
#include <cuda_runtime.h>
#include <math.h>

#define CB 16
#define CN 512
#define CD 256
#define CH 8
#define CDH 32
#define CDFF 1024
#define CL 2
#define NEG_INF_F (-1e9f)

// ---------------- scratch (static device allocations: allowed) ----------------
static __device__ float g_x [CB*CN*CD];
static __device__ float g_h [CB*CN*CD];
static __device__ float g_q [CB*CN*CD];
static __device__ float g_k [CB*CN*CD];
static __device__ float g_v [CB*CN*CD];
static __device__ float g_o [CB*CN*CD];
static __device__ float g_t [CB*CN*CD];
static __device__ float g_ff[CB*CN*CDFF];
static __device__ float g_alpha[CB*CN*CN];
static __device__ float g_e1[CB*CN];
static __device__ float g_e2[CB*CN];

// ---------------- generic strided-batched GEMM ----------------
// C = act( scale * A@B(^T) + bias ), 64x64 tile, BK=16, 256 threads, 4x4 per thread.
// Per-batch offsets: off = (z/div)*s1 + (z%div)*s2   (div>=1)
__global__ void gemm_kernel(const float* __restrict__ A, const float* __restrict__ B,
                            const float* __restrict__ bias, float* __restrict__ C,
                            int M, int Nc, int K, int lda, int ldb, int ldc,
                            long sA1, long sA2, int divA,
                            long sB1, long sB2, int divB,
                            long sC1, long sC2, int divC,
                            float scale, int act, int transB)
{
    const int bz = blockIdx.z;
    A += (long)(bz / divA) * sA1 + (long)(bz % divA) * sA2;
    B += (long)(bz / divB) * sB1 + (long)(bz % divB) * sB2;
    C += (long)(bz / divC) * sC1 + (long)(bz % divC) * sC2;

    __shared__ float As[16][64];   // [k][m]
    __shared__ float Bs[16][64];   // [k][n]

    const int tid = threadIdx.x;
    const int tx = tid & 15;       // 0..15  -> n-quad
    const int ty = tid >> 4;       // 0..15  -> m-quad
    const int row0 = blockIdx.y * 64;
    const int col0 = blockIdx.x * 64;

    float acc[4][4];
#pragma unroll
    for (int i = 0; i < 4; i++)
#pragma unroll
        for (int j = 0; j < 4; j++) acc[i][j] = 0.f;

    for (int k0 = 0; k0 < K; k0 += 16) {
        // load A tile (As[k][m]) - coalesced over k
        {
            const int k = tid & 15;
            const int gk = k0 + k;
#pragma unroll
            for (int p = 0; p < 4; p++) {
                const int m = (tid >> 4) + p * 16;
                const int gm = row0 + m;
                As[k][m] = (gm < M && gk < K) ? A[(long)gm * lda + gk] : 0.f;
            }
        }
        // load B tile (Bs[k][n])
        if (!transB) {
            const int n = tid & 63;
            const int gn = col0 + n;
#pragma unroll
            for (int p = 0; p < 4; p++) {
                const int k = (tid >> 6) + p * 4;
                const int gk = k0 + k;
                Bs[k][n] = (gk < K && gn < Nc) ? B[(long)gk * ldb + gn] : 0.f;
            }
        } else {
            const int k = tid & 15;
            const int gk = k0 + k;
#pragma unroll
            for (int p = 0; p < 4; p++) {
                const int n = (tid >> 4) + p * 16;
                const int gn = col0 + n;
                Bs[k][n] = (gn < Nc && gk < K) ? B[(long)gn * ldb + gk] : 0.f;
            }
        }
        __syncthreads();

#pragma unroll
        for (int kk = 0; kk < 16; kk++) {
            float4 a4 = *reinterpret_cast<const float4*>(&As[kk][ty * 4]);
            float4 b4 = *reinterpret_cast<const float4*>(&Bs[kk][tx * 4]);
            const float a[4] = {a4.x, a4.y, a4.z, a4.w};
            const float b[4] = {b4.x, b4.y, b4.z, b4.w};
#pragma unroll
            for (int i = 0; i < 4; i++)
#pragma unroll
                for (int j = 0; j < 4; j++) acc[i][j] = fmaf(a[i], b[j], acc[i][j]);
        }
        __syncthreads();
    }

#pragma unroll
    for (int i = 0; i < 4; i++) {
        const int gm = row0 + ty * 4 + i;
        if (gm >= M) continue;
#pragma unroll
        for (int j = 0; j < 4; j++) {
            const int gn = col0 + tx * 4 + j;
            if (gn >= Nc) continue;
            float vv = acc[i][j] * scale;
            if (bias) vv += bias[gn];
            if (act == 1) vv = fmaxf(vv, 0.f);
            else if (act == 2) vv = (vv > 0.f) ? vv : expm1f(vv);
            C[(long)gm * ldc + gn] = vv;
        }
    }
}

static inline void run_gemm(const float* A, const float* B, const float* bias, float* C,
                            int M, int Nc, int K, int lda, int ldb, int ldc,
                            int batch,
                            long sA1, long sA2, int divA,
                            long sB1, long sB2, int divB,
                            long sC1, long sC2, int divC,
                            float scale, int act, int transB)
{
    dim3 g((Nc + 63) / 64, (M + 63) / 64, batch);
    gemm_kernel<<<g, 256>>>(A, B, bias, C, M, Nc, K, lda, ldb, ldc,
                            sA1, sA2, divA, sB1, sB2, divB, sC1, sC2, divC,
                            scale, act, transB);
}

// ---------------- small fused kernels ----------------

__global__ void embed_kernel(const int* __restrict__ node, const float* __restrict__ embed,
                             float* __restrict__ x)
{
    const int row = blockIdx.x;          // B*N
    const int d = threadIdx.x;           // 256
    const int idx = node[row];
    x[(long)row * CD + d] = embed[(long)idx * CD + d];
}

// e1 = h@a1, e2 = h@a2 per row
__global__ void e12_kernel(const float* __restrict__ h, const float* __restrict__ a1,
                           const float* __restrict__ a2, float* __restrict__ e1,
                           float* __restrict__ e2)
{
    const int row = blockIdx.x;
    const int d = threadIdx.x;
    __shared__ float s1[256], s2[256];
    const float hv = h[(long)row * CD + d];
    s1[d] = hv * a1[d];
    s2[d] = hv * a2[d];
    __syncthreads();
    for (int off = 128; off > 0; off >>= 1) {
        if (d < off) { s1[d] += s1[d + off]; s2[d] += s2[d + off]; }
        __syncthreads();
    }
    if (d == 0) { e1[row] = s1[0]; e2[row] = s2[0]; }
}

// alpha[b,i,:] = softmax_j( mask(adj, leakyrelu(e1_i + e2_j)) )
__global__ void gat_softmax_kernel(const float* __restrict__ e1, const float* __restrict__ e2,
                                   const int* __restrict__ edge, float* __restrict__ alpha)
{
    const int row = blockIdx.x;          // b*N + i
    const int b = row / CN;
    const int t = threadIdx.x;           // 256, handles 2 j each
    __shared__ float red[256];
    const float ei = e1[row];

    float vals[2];
#pragma unroll
    for (int p = 0; p < 2; p++) {
        const int j = t + p * 256;
        float e = ei + e2[b * CN + j];
        e = (e >= 0.f) ? e : 0.2f * e;
        const bool adj = edge[(long)row * CN + j] > 0;
        vals[p] = adj ? e : NEG_INF_F;
    }
    // max
    red[t] = fmaxf(vals[0], vals[1]);
    __syncthreads();
    for (int off = 128; off > 0; off >>= 1) {
        if (t < off) red[t] = fmaxf(red[t], red[t + off]);
        __syncthreads();
    }
    const float m = red[0];
    __syncthreads();
    float ex[2];
    ex[0] = __expf(vals[0] - m);
    ex[1] = __expf(vals[1] - m);
    red[t] = ex[0] + ex[1];
    __syncthreads();
    for (int off = 128; off > 0; off >>= 1) {
        if (t < off) red[t] += red[t + off];
        __syncthreads();
    }
    const float inv = 1.f / red[0];
#pragma unroll
    for (int p = 0; p < 2; p++) {
        const int j = t + p * 256;
        alpha[(long)row * CN + j] = ex[p] * inv;
    }
}

// softmax over last dim of scores [B,H,N,N] in place, with +mask*NEG_INF
__global__ void mha_softmax_kernel(float* __restrict__ s, const int* __restrict__ mask)
{
    const int r = blockIdx.x;            // b*H*N + h*N + i
    const int b = r / (CH * CN);
    const int t = threadIdx.x;           // 256, 2 j each
    __shared__ float red[256];
    float* srow = s + (long)r * CN;

    float vals[2];
#pragma unroll
    for (int p = 0; p < 2; p++) {
        const int j = t + p * 256;
        vals[p] = srow[j] + (float)mask[b * CN + j] * NEG_INF_F;
    }
    red[t] = fmaxf(vals[0], vals[1]);
    __syncthreads();
    for (int off = 128; off > 0; off >>= 1) {
        if (t < off) red[t] = fmaxf(red[t], red[t + off]);
        __syncthreads();
    }
    const float m = red[0];
    __syncthreads();
    float ex[2];
    ex[0] = __expf(vals[0] - m);
    ex[1] = __expf(vals[1] - m);
    red[t] = ex[0] + ex[1];
    __syncthreads();
    for (int off = 128; off > 0; off >>= 1) {
        if (t < off) red[t] += red[t + off];
        __syncthreads();
    }
    const float inv = 1.f / red[0];
#pragma unroll
    for (int p = 0; p < 2; p++) {
        const int j = t + p * 256;
        srow[j] = ex[p] * inv;
    }
}

// x = x*sqrt(D) + PE(n,d)
__global__ void scale_pe_kernel(float* __restrict__ x)
{
    const int row = blockIdx.x;          // b*N + n
    const int n = row % CN;
    const int d = threadIdx.x;
    const float expo = (2.0f * (float)(d >> 1)) / (float)CD;
    const float angle = (float)n * powf(10000.0f, -expo);
    const float pe = (d & 1) ? cosf(angle) : sinf(angle);
    const long idx = (long)row * CD + d;
    x[idx] = x[idx] * 16.0f + pe;       // sqrt(256) = 16
}

// out = LN(x + delta) * g + b  (row = B*N, D=256, one thread per element)
__global__ void ln_kernel(const float* __restrict__ x, const float* __restrict__ delta,
                          const float* __restrict__ g, const float* __restrict__ bb,
                          float* __restrict__ out)
{
    const int row = blockIdx.x;
    const int d = threadIdx.x;
    __shared__ float red[256];
    const long idx = (long)row * CD + d;
    const float v = x[idx] + delta[idx];
    red[d] = v;
    __syncthreads();
    for (int off = 128; off > 0; off >>= 1) {
        if (d < off) red[d] += red[d + off];
        __syncthreads();
    }
    const float mu = red[0] * (1.0f / CD);
    __syncthreads();
    const float c = v - mu;
    red[d] = c * c;
    __syncthreads();
    for (int off = 128; off > 0; off >>= 1) {
        if (d < off) red[d] += red[d + off];
        __syncthreads();
    }
    const float var = red[0] * (1.0f / CD);
    out[idx] = c * rsqrtf(var + 1e-6f) * g[d] + bb[d];
}

__global__ void copy_kernel(const float* __restrict__ src, float* __restrict__ dst, long n)
{
    const long i = (long)blockIdx.x * blockDim.x + threadIdx.x;
    if (i < n) dst[i] = src[i];
}

// ---------------- launch ----------------
extern "C" void kernel_launch(void* const* d_in, const int* in_sizes, int n_in,
                              void* d_out, int out_size)
{
    const int*   node  = (const int*)  d_in[0];
    const int*   edge  = (const int*)  d_in[1];
    const int*   mask  = (const int*)  d_in[2];
    const float* embed = (const float*)d_in[4];
    const float* Wg    = (const float*)d_in[5];
    const float* a1    = (const float*)d_in[6];
    const float* a2    = (const float*)d_in[7];
    const float* Wq    = (const float*)d_in[8];
    const float* bq    = (const float*)d_in[9];
    const float* Wk    = (const float*)d_in[10];
    const float* bk    = (const float*)d_in[11];
    const float* Wv    = (const float*)d_in[12];
    const float* bv    = (const float*)d_in[13];
    const float* Wo    = (const float*)d_in[14];
    const float* bo    = (const float*)d_in[15];
    const float* W1    = (const float*)d_in[16];
    const float* b1    = (const float*)d_in[17];
    const float* W2    = (const float*)d_in[18];
    const float* b2    = (const float*)d_in[19];
    const float* ln1g  = (const float*)d_in[20];
    const float* ln1b  = (const float*)d_in[21];
    const float* ln2g  = (const float*)d_in[22];
    const float* ln2b  = (const float*)d_in[23];

    float *x, *h, *q, *k, *v, *o, *t, *ff, *alpha, *e1, *e2;
    cudaGetSymbolAddress((void**)&x,  g_x);
    cudaGetSymbolAddress((void**)&h,  g_h);
    cudaGetSymbolAddress((void**)&q,  g_q);
    cudaGetSymbolAddress((void**)&k,  g_k);
    cudaGetSymbolAddress((void**)&v,  g_v);
    cudaGetSymbolAddress((void**)&o,  g_o);
    cudaGetSymbolAddress((void**)&t,  g_t);
    cudaGetSymbolAddress((void**)&ff, g_ff);
    cudaGetSymbolAddress((void**)&alpha, g_alpha);
    cudaGetSymbolAddress((void**)&e1, g_e1);
    cudaGetSymbolAddress((void**)&e2, g_e2);

    float* out_x    = (float*)d_out;                       // [B,N,D]
    float* out_attn = (float*)d_out + (long)CB * CN * CD;  // [B,H,N,N]

    const int M  = CB * CN;          // 8192
    const long ND = (long)CN * CD;   // per-batch x stride
    const long NN = (long)CN * CN;

    // ---- embedding ----
    embed_kernel<<<M, CD>>>(node, embed, x);

    // ---- GAT hops ----
    for (int hop = 0; hop < 2; hop++) {
        run_gemm(x, Wg, nullptr, h, M, CD, CD, CD, CD, CD,
                 1, 0, 0, 1, 0, 0, 1, 0, 0, 1, 1.0f, 0, 0);
        e12_kernel<<<M, CD>>>(h, a1, a2, e1, e2);
        gat_softmax_kernel<<<M, 256>>>(e1, e2, edge, alpha);
        // x = elu(alpha @ h), batched over B
        run_gemm(alpha, h, nullptr, x, CN, CD, CN, CN, CD, CD,
                 CB, NN, 0, 1, ND, 0, 1, ND, 0, 1, 1.0f, 2, 0);
    }

    // ---- scale + positional encoding ----
    scale_pe_kernel<<<M, CD>>>(x);

    // ---- transformer layers ----
    const float inv_sqrt_dh = 0.17677669529663687f; // 1/sqrt(32)
    for (int l = 0; l < CL; l++) {
        const long wOff = (long)l * CD * CD;
        run_gemm(x, Wq + wOff, bq + l * CD, q, M, CD, CD, CD, CD, CD,
                 1, 0, 0, 1, 0, 0, 1, 0, 0, 1, 1.0f, 0, 0);
        run_gemm(x, Wk + wOff, bk + l * CD, k, M, CD, CD, CD, CD, CD,
                 1, 0, 0, 1, 0, 0, 1, 0, 0, 1, 1.0f, 0, 0);
        run_gemm(x, Wv + wOff, bv + l * CD, v, M, CD, CD, CD, CD, CD,
                 1, 0, 0, 1, 0, 0, 1, 0, 0, 1, 1.0f, 0, 0);

        // scores = q @ k^T / sqrt(dh)   batched over B*H, written into d_out attn region
        run_gemm(q, k, nullptr, out_attn, CN, CN, CDH, CD, CD, CN,
                 CB * CH, ND, CDH, CH,   // A: z/H -> batch, z%H -> head col offset
                 ND, CDH, CH,
                 NN, 0, 1,
                 inv_sqrt_dh, 0, 1);

        mha_softmax_kernel<<<CB * CH * CN, 256>>>(out_attn, mask);

        // o = attn @ v   (per head, Nc = 32)
        run_gemm(out_attn, v, nullptr, o, CN, CDH, CN, CN, CD, CD,
                 CB * CH, NN, 0, 1,
                 ND, CDH, CH,
                 ND, CDH, CH,
                 1.0f, 0, 0);

        // t = o @ Wo + bo ; x = LN(x + t)
        run_gemm(o, Wo + wOff, bo + l * CD, t, M, CD, CD, CD, CD, CD,
                 1, 0, 0, 1, 0, 0, 1, 0, 0, 1, 1.0f, 0, 0);
        ln_kernel<<<M, CD>>>(x, t, ln1g + l * CD, ln1b + l * CD, x);

        // FFN
        run_gemm(x, W1 + (long)l * CD * CDFF, b1 + l * CDFF, ff, M, CDFF, CD,
                 CD, CDFF, CDFF, 1, 0, 0, 1, 0, 0, 1, 0, 0, 1, 1.0f, 1, 0);
        run_gemm(ff, W2 + (long)l * CDFF * CD, b2 + l * CD, t, M, CD, CDFF,
                 CDFF, CD, CD, 1, 0, 0, 1, 0, 0, 1, 0, 0, 1, 1.0f, 0, 0);
        ln_kernel<<<M, CD>>>(x, t, ln2g + l * CD, ln2b + l * CD, x);
    }

    // ---- write x output ----
    const long xcount = (long)CB * CN * CD;
    copy_kernel<<<(int)((xcount + 255) / 256), 256>>>(x, out_x, xcount);
}

// round 4
// speedup vs baseline: 1.9958x; 1.9958x over previous
#include <cuda_runtime.h>
#include <cuda_bf16.h>
#include <math.h>
#include <stdint.h>

#define CB 16
#define CN 512
#define CD 256
#define CH 8
#define CDFF 1024
#define CL 2
#define NEG_INF_F (-1e9f)

// ---------------- scratch ----------------
static __device__ __align__(256) float g_x [CB*CN*CD];
static __device__ __align__(256) float g_h [CB*CN*CD];
static __device__ __align__(256) float g_q [CB*CN*CD];
static __device__ __align__(256) float g_k [CB*CN*CD];
static __device__ __align__(256) float g_v [CB*CN*CD];
static __device__ __align__(256) float g_o [CB*CN*CD];
static __device__ __align__(256) float g_t [CB*CN*CD];
static __device__ __align__(256) float g_ff[CB*CN*CDFF];
static __device__ __align__(256) float g_e1[CB*CN];
static __device__ __align__(256) float g_e2[CB*CN];

static __device__ __align__(256) __nv_bfloat16 g_x3 [CB*CN*768];
static __device__ __align__(256) __nv_bfloat16 g_o3 [CB*CN*768];
static __device__ __align__(256) __nv_bfloat16 g_ff3[CB*CN*3072];
static __device__ __align__(256) __nv_bfloat16 g_h3t[CB*CD*1536];
static __device__ __align__(256) __nv_bfloat16 g_al3[CB*CN*1536];
static __device__ __align__(256) __nv_bfloat16 g_at3[CB*CH*CN*1536];
static __device__ __align__(256) __nv_bfloat16 g_q3 [CB*CH*CN*128];
static __device__ __align__(256) __nv_bfloat16 g_k3 [CB*CH*CN*128];
static __device__ __align__(256) __nv_bfloat16 g_v3t[CB*CH*32*1536];
static __device__ __align__(256) __nv_bfloat16 g_wb [1024*3072];
static __device__ __align__(256) __nv_bfloat16 g_wg3[CD*768];

__device__ __forceinline__ void bf_split_A(float v, __nv_bfloat16& a, __nv_bfloat16& b, __nv_bfloat16& c) {
    a = __float2bfloat16(v);
    b = __float2bfloat16(v - __bfloat162float(a));
    c = a;                                   // A pattern: hi, lo, hi
}

// ---------------- mma.sync bf16 GEMM ----------------
// C[128 x TN] per block. A [M,K3] row-major, B [N,K3] row-major (C = A @ B^T).
// 8 warps: (128/WM) x (TN/WN) grid, each warp WM x WN via m16n8k16.
template<int TN, int WM, int WN>
__global__ __launch_bounds__(256)
void gemm_mma(const __nv_bfloat16* __restrict__ A, const __nv_bfloat16* __restrict__ B,
              const float* __restrict__ bias, float* __restrict__ C,
              int lda, int ldb, int ldc, int K3,
              long strA, long strB, long sC1, long sC2, int divC,
              float scale, int act)
{
    constexpr int BK = 64;
    constexpr int LDS = BK + 8;          // 72 bf16 row stride: conflict-free
    constexpr int MT = WM / 16;
    constexpr int NT = WN / 8;
    constexpr int WCOLS = TN / WN;
    __shared__ __nv_bfloat16 shA[128][LDS];
    __shared__ __nv_bfloat16 shB[TN][LDS];

    const long z = blockIdx.z;
    A += z * strA;
    B += z * strB;
    C += (z / divC) * sC1 + (z % divC) * sC2;
    const int row0 = blockIdx.y * 128;
    const int col0 = blockIdx.x * TN;

    const int tid = threadIdx.x;
    const int w = tid >> 5, lane = tid & 31;
    const int wr = w / WCOLS, wc = w % WCOLS;
    const int gid = lane >> 2, tig = lane & 3;

    float acc[MT][NT][4];
#pragma unroll
    for (int mt = 0; mt < MT; mt++)
#pragma unroll
        for (int nt = 0; nt < NT; nt++)
#pragma unroll
            for (int i = 0; i < 4; i++) acc[mt][nt][i] = 0.f;

    for (int k0 = 0; k0 < K3; k0 += BK) {
        // A tile: 128x64 bf16 = 1024 uint4, 4 per thread
#pragma unroll
        for (int i = 0; i < 4; i++) {
            const int idx = i * 256 + tid;
            const int r = idx >> 3, kc = (idx & 7) * 8;
            uint4 vv = *reinterpret_cast<const uint4*>(A + (long)(row0 + r) * lda + k0 + kc);
            *reinterpret_cast<uint4*>(&shA[r][kc]) = vv;
        }
        // B tile: TN x 64
#pragma unroll
        for (int i = 0; i < TN * BK / 8 / 256; i++) {
            const int idx = i * 256 + tid;
            const int r = idx >> 3, kc = (idx & 7) * 8;
            uint4 vv = *reinterpret_cast<const uint4*>(B + (long)(col0 + r) * ldb + k0 + kc);
            *reinterpret_cast<uint4*>(&shB[r][kc]) = vv;
        }
        __syncthreads();

#pragma unroll
        for (int kk = 0; kk < BK; kk += 16) {
            uint32_t af[MT][4], bfr[NT][2];
#pragma unroll
            for (int mt = 0; mt < MT; mt++) {
                const int r = wr * WM + mt * 16 + gid;
                af[mt][0] = *reinterpret_cast<const uint32_t*>(&shA[r][kk + tig * 2]);
                af[mt][1] = *reinterpret_cast<const uint32_t*>(&shA[r + 8][kk + tig * 2]);
                af[mt][2] = *reinterpret_cast<const uint32_t*>(&shA[r][kk + tig * 2 + 8]);
                af[mt][3] = *reinterpret_cast<const uint32_t*>(&shA[r + 8][kk + tig * 2 + 8]);
            }
#pragma unroll
            for (int nt = 0; nt < NT; nt++) {
                const int cidx = wc * WN + nt * 8 + gid;
                bfr[nt][0] = *reinterpret_cast<const uint32_t*>(&shB[cidx][kk + tig * 2]);
                bfr[nt][1] = *reinterpret_cast<const uint32_t*>(&shB[cidx][kk + tig * 2 + 8]);
            }
#pragma unroll
            for (int mt = 0; mt < MT; mt++)
#pragma unroll
                for (int nt = 0; nt < NT; nt++) {
                    asm volatile(
                        "mma.sync.aligned.m16n8k16.row.col.f32.bf16.bf16.f32 "
                        "{%0,%1,%2,%3}, {%4,%5,%6,%7}, {%8,%9}, {%0,%1,%2,%3};"
                        : "+f"(acc[mt][nt][0]), "+f"(acc[mt][nt][1]),
                          "+f"(acc[mt][nt][2]), "+f"(acc[mt][nt][3])
                        : "r"(af[mt][0]), "r"(af[mt][1]), "r"(af[mt][2]), "r"(af[mt][3]),
                          "r"(bfr[nt][0]), "r"(bfr[nt][1]));
                }
        }
        __syncthreads();
    }

    // epilogue
#pragma unroll
    for (int mt = 0; mt < MT; mt++) {
#pragma unroll
        for (int nt = 0; nt < NT; nt++) {
            const int r = row0 + wr * WM + mt * 16 + gid;
            const int cidx = col0 + wc * WN + nt * 8 + tig * 2;
            float b0 = bias ? bias[cidx] : 0.f;
            float b1 = bias ? bias[cidx + 1] : 0.f;
#pragma unroll
            for (int half = 0; half < 2; half++) {
                float v0 = acc[mt][nt][half * 2 + 0] * scale + b0;
                float v1 = acc[mt][nt][half * 2 + 1] * scale + b1;
                if (act == 1) { v0 = fmaxf(v0, 0.f); v1 = fmaxf(v1, 0.f); }
                else if (act == 2) {
                    v0 = (v0 > 0.f) ? v0 : expm1f(v0);
                    v1 = (v1 > 0.f) ? v1 : expm1f(v1);
                }
                *reinterpret_cast<float2*>(&C[(long)(r + half * 8) * ldc + cidx]) = make_float2(v0, v1);
            }
        }
    }
}

// ---------------- elementwise / split kernels ----------------

__global__ void split_rows(const float* __restrict__ in, __nv_bfloat16* __restrict__ out, int C)
{
    const long row = blockIdx.x;
    for (int c = threadIdx.x; c < C; c += blockDim.x) {
        __nv_bfloat16 h0, h1, h2;
        bf_split_A(in[row * C + c], h0, h1, h2);
        out[row * 3 * C + c] = h0;
        out[row * 3 * C + C + c] = h1;
        out[row * 3 * C + 2 * C + c] = h2;
    }
}

// in [R, C] (row stride irs) -> out [C, 3R] bf16 B-pattern [hi|hi|lo]; batched via z
__global__ void tsplitB(const float* __restrict__ in, __nv_bfloat16* __restrict__ out,
                        int irs, int R, long sIn1, long sIn2, int divIn, long sOut)
{
    __shared__ float tile[128][33];
    const long z = blockIdx.z;
    in  += (z / divIn) * sIn1 + (z % divIn) * sIn2;
    out += z * sOut;
    const int r0 = blockIdx.x * 128, c0 = blockIdx.y * 32;
    for (int i = threadIdx.x; i < 128 * 32; i += 256) {
        int rr = i >> 5, cc = i & 31;
        tile[rr][cc] = in[(long)(r0 + rr) * irs + c0 + cc];
    }
    __syncthreads();
    for (int i = threadIdx.x; i < 32 * 128; i += 256) {
        int cc = i >> 7, rr = i & 127;
        float v = tile[rr][cc];
        __nv_bfloat16 hi = __float2bfloat16(v);
        __nv_bfloat16 lo = __float2bfloat16(v - __bfloat162float(hi));
        long ob = (long)(c0 + cc) * (3L * R) + (r0 + rr);
        out[ob] = hi; out[ob + R] = hi; out[ob + 2L * R] = lo;
    }
}

__global__ void qk_split(const float* __restrict__ q, const float* __restrict__ k,
                         __nv_bfloat16* __restrict__ q3, __nv_bfloat16* __restrict__ k3)
{
    const int row = blockIdx.x;
    const int b = row >> 9, i = row & 511;
    const int d = threadIdx.x;
    const int h = d >> 5, dd = d & 31;
    const long base = ((long)(b * CH + h) * CN + i) * 128;
    const __nv_bfloat16 zero = __float2bfloat16(0.f);
    float qv = q[(long)row * CD + d];
    float kv = k[(long)row * CD + d];
    __nv_bfloat16 qh = __float2bfloat16(qv);
    __nv_bfloat16 ql = __float2bfloat16(qv - __bfloat162float(qh));
    __nv_bfloat16 kh = __float2bfloat16(kv);
    __nv_bfloat16 kl = __float2bfloat16(kv - __bfloat162float(kh));
    q3[base + dd] = qh;  q3[base + 32 + dd] = ql; q3[base + 64 + dd] = qh; q3[base + 96 + dd] = zero;
    k3[base + dd] = kh;  k3[base + 32 + dd] = kh; k3[base + 64 + dd] = kl; k3[base + 96 + dd] = zero;
}

__global__ void embed_kernel(const int* __restrict__ node, const float* __restrict__ embed,
                             float* __restrict__ x)
{
    const int row = blockIdx.x;
    const int d = threadIdx.x;
    x[(long)row * CD + d] = embed[(long)node[row] * CD + d];
}

__global__ void e12_kernel(const float* __restrict__ h, const float* __restrict__ a1,
                           const float* __restrict__ a2, float* __restrict__ e1, float* __restrict__ e2)
{
    const int row = blockIdx.x;
    const int d = threadIdx.x;
    __shared__ float s1[256], s2[256];
    const float hv = h[(long)row * CD + d];
    s1[d] = hv * a1[d];
    s2[d] = hv * a2[d];
    __syncthreads();
    for (int off = 128; off > 0; off >>= 1) {
        if (d < off) { s1[d] += s1[d + off]; s2[d] += s2[d + off]; }
        __syncthreads();
    }
    if (d == 0) { e1[row] = s1[0]; e2[row] = s2[0]; }
}

__global__ void gat_softmax_kernel(const float* __restrict__ e1, const float* __restrict__ e2,
                                   const int* __restrict__ edge, __nv_bfloat16* __restrict__ al3)
{
    const int row = blockIdx.x;
    const int b = row / CN;
    const int t = threadIdx.x;
    __shared__ float red[256];
    const float ei = e1[row];
    float vals[2];
#pragma unroll
    for (int p = 0; p < 2; p++) {
        const int j = t + p * 256;
        float e = ei + e2[b * CN + j];
        e = (e >= 0.f) ? e : 0.2f * e;
        vals[p] = (edge[(long)row * CN + j] > 0) ? e : NEG_INF_F;
    }
    red[t] = fmaxf(vals[0], vals[1]);
    __syncthreads();
    for (int off = 128; off > 0; off >>= 1) { if (t < off) red[t] = fmaxf(red[t], red[t + off]); __syncthreads(); }
    const float m = red[0];
    __syncthreads();
    float ex[2] = {__expf(vals[0] - m), __expf(vals[1] - m)};
    red[t] = ex[0] + ex[1];
    __syncthreads();
    for (int off = 128; off > 0; off >>= 1) { if (t < off) red[t] += red[t + off]; __syncthreads(); }
    const float inv = 1.f / red[0];
    const long b3 = (long)row * 1536;
#pragma unroll
    for (int p = 0; p < 2; p++) {
        const int j = t + p * 256;
        __nv_bfloat16 h0, h1, h2;
        bf_split_A(ex[p] * inv, h0, h1, h2);
        al3[b3 + j] = h0; al3[b3 + 512 + j] = h1; al3[b3 + 1024 + j] = h2;
    }
}

__global__ void mha_softmax_kernel(float* __restrict__ s, const int* __restrict__ mask,
                                   __nv_bfloat16* __restrict__ at3)
{
    const int r = blockIdx.x;
    const int b = r / (CH * CN);
    const int t = threadIdx.x;
    __shared__ float red[256];
    float* srow = s + (long)r * CN;
    float vals[2];
#pragma unroll
    for (int p = 0; p < 2; p++) {
        const int j = t + p * 256;
        vals[p] = srow[j] + (float)mask[b * CN + j] * NEG_INF_F;
    }
    red[t] = fmaxf(vals[0], vals[1]);
    __syncthreads();
    for (int off = 128; off > 0; off >>= 1) { if (t < off) red[t] = fmaxf(red[t], red[t + off]); __syncthreads(); }
    const float m = red[0];
    __syncthreads();
    float ex[2] = {__expf(vals[0] - m), __expf(vals[1] - m)};
    red[t] = ex[0] + ex[1];
    __syncthreads();
    for (int off = 128; off > 0; off >>= 1) { if (t < off) red[t] += red[t + off]; __syncthreads(); }
    const float inv = 1.f / red[0];
    const long b3 = (long)r * 1536;
#pragma unroll
    for (int p = 0; p < 2; p++) {
        const int j = t + p * 256;
        const float pr = ex[p] * inv;
        srow[j] = pr;
        __nv_bfloat16 h0, h1, h2;
        bf_split_A(pr, h0, h1, h2);
        at3[b3 + j] = h0; at3[b3 + 512 + j] = h1; at3[b3 + 1024 + j] = h2;
    }
}

__global__ void scale_pe_kernel(float* __restrict__ x)
{
    const int row = blockIdx.x;
    const int n = row % CN;
    const int d = threadIdx.x;
    const float expo = (2.0f * (float)(d >> 1)) / (float)CD;
    const float angle = (float)n * powf(10000.0f, -expo);
    const float pe = (d & 1) ? cosf(angle) : sinf(angle);
    const long idx = (long)row * CD + d;
    x[idx] = x[idx] * 16.0f + pe;
}

__global__ void ln_kernel(const float* __restrict__ x, const float* __restrict__ delta,
                          const float* __restrict__ g, const float* __restrict__ bb,
                          float* __restrict__ out)
{
    const int row = blockIdx.x;
    const int d = threadIdx.x;
    __shared__ float red[256];
    const long idx = (long)row * CD + d;
    const float v = x[idx] + delta[idx];
    red[d] = v;
    __syncthreads();
    for (int off = 128; off > 0; off >>= 1) { if (d < off) red[d] += red[d + off]; __syncthreads(); }
    const float mu = red[0] * (1.0f / CD);
    __syncthreads();
    const float c = v - mu;
    red[d] = c * c;
    __syncthreads();
    for (int off = 128; off > 0; off >>= 1) { if (d < off) red[d] += red[d + off]; __syncthreads(); }
    const float var = red[0] * (1.0f / CD);
    out[idx] = c * rsqrtf(var + 1e-6f) * g[d] + bb[d];
}

__global__ void copy_kernel(const float* __restrict__ src, float* __restrict__ dst, long n)
{
    const long i = (long)blockIdx.x * blockDim.x + threadIdx.x;
    if (i < n) dst[i] = src[i];
}

// ---------------- host ----------------
static void launch_gemm(const __nv_bfloat16* A, const __nv_bfloat16* B, const float* bias, float* C,
                        int M, int N, int K3, int lda, int ldb, int ldc,
                        long sA, long sB, long sC1, long sC2, int divC,
                        float scale, int act, int batch)
{
    if (N % 128 == 0) {
        dim3 g(N / 128, M / 128, batch);
        gemm_mma<128, 64, 32><<<g, 256>>>(A, B, bias, C, lda, ldb, ldc, K3,
                                          sA, sB, sC1, sC2, divC, scale, act);
    } else {
        dim3 g(N / 32, M / 128, batch);
        gemm_mma<32, 32, 16><<<g, 256>>>(A, B, bias, C, lda, ldb, ldc, K3,
                                         sA, sB, sC1, sC2, divC, scale, act);
    }
}

extern "C" void kernel_launch(void* const* d_in, const int* in_sizes, int n_in,
                              void* d_out, int out_size)
{
    const int*   node  = (const int*)  d_in[0];
    const int*   edge  = (const int*)  d_in[1];
    const int*   mask  = (const int*)  d_in[2];
    const float* embed = (const float*)d_in[4];
    const float* Wg    = (const float*)d_in[5];
    const float* a1    = (const float*)d_in[6];
    const float* a2    = (const float*)d_in[7];
    const float* Wq    = (const float*)d_in[8];
    const float* bq    = (const float*)d_in[9];
    const float* Wk    = (const float*)d_in[10];
    const float* bk    = (const float*)d_in[11];
    const float* Wv    = (const float*)d_in[12];
    const float* bv    = (const float*)d_in[13];
    const float* Wo    = (const float*)d_in[14];
    const float* bo    = (const float*)d_in[15];
    const float* W1    = (const float*)d_in[16];
    const float* b1    = (const float*)d_in[17];
    const float* W2    = (const float*)d_in[18];
    const float* b2    = (const float*)d_in[19];
    const float* ln1g  = (const float*)d_in[20];
    const float* ln1b  = (const float*)d_in[21];
    const float* ln2g  = (const float*)d_in[22];
    const float* ln2b  = (const float*)d_in[23];

    float *x, *h, *q, *k, *v, *o, *t, *ff, *e1, *e2;
    __nv_bfloat16 *x3, *o3, *ff3, *h3t, *al3, *at3, *q3, *k3, *v3t, *wb, *wg3;
    cudaGetSymbolAddress((void**)&x, g_x);   cudaGetSymbolAddress((void**)&h, g_h);
    cudaGetSymbolAddress((void**)&q, g_q);   cudaGetSymbolAddress((void**)&k, g_k);
    cudaGetSymbolAddress((void**)&v, g_v);   cudaGetSymbolAddress((void**)&o, g_o);
    cudaGetSymbolAddress((void**)&t, g_t);   cudaGetSymbolAddress((void**)&ff, g_ff);
    cudaGetSymbolAddress((void**)&e1, g_e1); cudaGetSymbolAddress((void**)&e2, g_e2);
    cudaGetSymbolAddress((void**)&x3, g_x3); cudaGetSymbolAddress((void**)&o3, g_o3);
    cudaGetSymbolAddress((void**)&ff3, g_ff3); cudaGetSymbolAddress((void**)&h3t, g_h3t);
    cudaGetSymbolAddress((void**)&al3, g_al3); cudaGetSymbolAddress((void**)&at3, g_at3);
    cudaGetSymbolAddress((void**)&q3, g_q3); cudaGetSymbolAddress((void**)&k3, g_k3);
    cudaGetSymbolAddress((void**)&v3t, g_v3t); cudaGetSymbolAddress((void**)&wb, g_wb);
    cudaGetSymbolAddress((void**)&wg3, g_wg3);

    float* out_x    = (float*)d_out;
    float* out_attn = (float*)d_out + (long)CB * CN * CD;

    const int M = CB * CN;                 // 8192
    const long ND = (long)CN * CD;         // 131072
    const float inv_sqrt_dh = 0.17677669529663687f;

    embed_kernel<<<M, CD>>>(node, embed, x);
    tsplitB<<<dim3(2, 8, 1), 256>>>(Wg, wg3, CD, CD, 0, 0, 1, 0);

    for (int hop = 0; hop < 2; hop++) {
        split_rows<<<M, 256>>>(x, x3, CD);
        launch_gemm(x3, wg3, nullptr, h, M, CD, 768, 768, 768, CD,
                    0, 0, 0, 0, 1, 1.f, 0, 1);
        tsplitB<<<dim3(4, 8, CB), 256>>>(h, h3t, CD, CN, ND, 0, 1, (long)CD * 1536);
        e12_kernel<<<M, CD>>>(h, a1, a2, e1, e2);
        gat_softmax_kernel<<<M, 256>>>(e1, e2, edge, al3);
        launch_gemm(al3, h3t, nullptr, x, CN, CD, 1536, 1536, 1536, CD,
                    (long)CN * 1536, (long)CD * 1536, ND, 0, 1, 1.f, 2, CB);
    }

    scale_pe_kernel<<<M, CD>>>(x);

    for (int l = 0; l < CL; l++) {
        const long wOff = (long)l * CD * CD;
        split_rows<<<M, 256>>>(x, x3, CD);

        tsplitB<<<dim3(2, 8, 1), 256>>>(Wq + wOff, wb, CD, CD, 0, 0, 1, 0);
        launch_gemm(x3, wb, bq + l * CD, q, M, CD, 768, 768, 768, CD, 0, 0, 0, 0, 1, 1.f, 0, 1);
        tsplitB<<<dim3(2, 8, 1), 256>>>(Wk + wOff, wb, CD, CD, 0, 0, 1, 0);
        launch_gemm(x3, wb, bk + l * CD, k, M, CD, 768, 768, 768, CD, 0, 0, 0, 0, 1, 1.f, 0, 1);
        tsplitB<<<dim3(2, 8, 1), 256>>>(Wv + wOff, wb, CD, CD, 0, 0, 1, 0);
        launch_gemm(x3, wb, bv + l * CD, v, M, CD, 768, 768, 768, CD, 0, 0, 0, 0, 1, 1.f, 0, 1);

        qk_split<<<M, 256>>>(q, k, q3, k3);
        tsplitB<<<dim3(4, 1, CB * CH), 256>>>(v, v3t, CD, CN, ND, 32, CH, 32L * 1536);

        // scores = q @ k^T / sqrt(dh)  (batched over B*H) -> out_attn
        launch_gemm(q3, k3, nullptr, out_attn, CN, CN, 128, 128, 128, CN,
                    (long)CN * 128, (long)CN * 128, (long)CN * CN, 0, 1,
                    inv_sqrt_dh, 0, CB * CH);

        mha_softmax_kernel<<<CB * CH * CN, 256>>>(out_attn, mask, at3);

        // o = attn @ v  (batched over B*H, N=32)
        launch_gemm(at3, v3t, nullptr, o, CN, 32, 1536, 1536, 1536, CD,
                    (long)CN * 1536, 32L * 1536, ND, 32, CH, 1.f, 0, CB * CH);

        tsplitB<<<dim3(2, 8, 1), 256>>>(Wo + wOff, wb, CD, CD, 0, 0, 1, 0);
        split_rows<<<M, 256>>>(o, o3, CD);
        launch_gemm(o3, wb, bo + l * CD, t, M, CD, 768, 768, 768, CD, 0, 0, 0, 0, 1, 1.f, 0, 1);
        ln_kernel<<<M, CD>>>(x, t, ln1g + l * CD, ln1b + l * CD, x);

        split_rows<<<M, 256>>>(x, x3, CD);
        tsplitB<<<dim3(2, 32, 1), 256>>>(W1 + (long)l * CD * CDFF, wb, CDFF, CD, 0, 0, 1, 0);
        launch_gemm(x3, wb, b1 + l * CDFF, ff, M, CDFF, 768, 768, 768, CDFF,
                    0, 0, 0, 0, 1, 1.f, 1, 1);
        split_rows<<<M, 256>>>(ff, ff3, CDFF);
        tsplitB<<<dim3(8, 8, 1), 256>>>(W2 + (long)l * CDFF * CD, wb, CD, CDFF, 0, 0, 1, 0);
        launch_gemm(ff3, wb, b2 + l * CD, t, M, CD, 3072, 3072, 3072, CD,
                    0, 0, 0, 0, 1, 1.f, 0, 1);
        ln_kernel<<<M, CD>>>(x, t, ln2g + l * CD, ln2b + l * CD, x);
    }

    const long xcount = (long)CB * CN * CD;
    copy_kernel<<<(int)((xcount + 255) / 256), 256>>>(x, out_x, xcount);
}

// round 5
// speedup vs baseline: 2.2576x; 1.1312x over previous
#include <cuda_runtime.h>
#include <cuda_bf16.h>
#include <math.h>
#include <stdint.h>

#define CB 16
#define CN 512
#define CD 256
#define CH 8
#define CDFF 1024
#define CL 2
#define NEG_INF_F (-1e9f)

// ---------------- scratch ----------------
static __device__ __align__(256) float g_x  [CB*CN*CD];
static __device__ __align__(256) float g_h  [CB*CN*CD];
static __device__ __align__(256) float g_qkv[CB*CN*768];
static __device__ __align__(256) float g_t  [CB*CN*CD];
static __device__ __align__(256) float g_ff [CB*CN*CDFF];
static __device__ __align__(256) float g_e1 [CB*CN];
static __device__ __align__(256) float g_e2 [CB*CN];
static __device__ __align__(256) float g_bias[768];

static __device__ __align__(256) __nv_bfloat16 g_x3 [CB*CN*768];
static __device__ __align__(256) __nv_bfloat16 g_o3 [CB*CN*768];
static __device__ __align__(256) __nv_bfloat16 g_ff3[CB*CN*3072];
static __device__ __align__(256) __nv_bfloat16 g_h3t[CB*CD*1536];
static __device__ __align__(256) __nv_bfloat16 g_al3[CB*CN*1536];
static __device__ __align__(256) __nv_bfloat16 g_at3[CB*CH*CN*1536];
static __device__ __align__(256) __nv_bfloat16 g_q3 [CB*CH*CN*128];
static __device__ __align__(256) __nv_bfloat16 g_k3 [CB*CH*CN*128];
static __device__ __align__(256) __nv_bfloat16 g_v3t[CB*CH*32*1536];
static __device__ __align__(256) __nv_bfloat16 g_wb [1024*3072];
static __device__ __align__(256) __nv_bfloat16 g_wg3[CD*768];

__device__ __forceinline__ void bf_split_A(float v, __nv_bfloat16& a, __nv_bfloat16& b, __nv_bfloat16& c) {
    a = __float2bfloat16(v);
    b = __float2bfloat16(v - __bfloat162float(a));
    c = a;                                   // A pattern: hi, lo, hi
}
__device__ __forceinline__ void cpa16(uint32_t s, const void* g) {
    asm volatile("cp.async.cg.shared.global [%0], [%1], 16;" :: "r"(s), "l"(g));
}

// ---------------- cp.async double-buffered mma.sync bf16 GEMM ----------------
// C[128 x TN] per block; A [M,K3], B [N,K3] row-major; C = A@B^T.
// Optional bf16x3 secondary output C3 (A-pattern split of the final value).
template<int TN, int WM, int WN>
__global__ __launch_bounds__(256)
void gemm_mma(const __nv_bfloat16* __restrict__ A, const __nv_bfloat16* __restrict__ B,
              const float* __restrict__ bias, float* __restrict__ C,
              int lda, int ldb, int ldc, int K3,
              long strA, long strB, long sC1, long sC2, int divC,
              float scale, int act,
              __nv_bfloat16* __restrict__ C3, long sC31, long sC32, int ldc3, int seg3)
{
    constexpr int BK = 64;
    constexpr int LDS = BK + 8;
    constexpr int MT = WM / 16;
    constexpr int NT = WN / 8;
    constexpr int WCOLS = TN / WN;
    constexpr int BITERS = TN / 32;          // B-tile uint4 loads per thread

    extern __shared__ __nv_bfloat16 smem[];
    __nv_bfloat16* sA = smem;                 // [2][128][LDS]
    __nv_bfloat16* sB = smem + 2 * 128 * LDS; // [2][TN][LDS]

    const long z = blockIdx.z;
    A += z * strA;
    B += z * strB;
    C += (z / divC) * sC1 + (z % divC) * sC2;
    if (C3) C3 += (z / divC) * sC31 + (z % divC) * sC32;
    const int row0 = blockIdx.y * 128;
    const int col0 = blockIdx.x * TN;

    const int tid = threadIdx.x;
    const int w = tid >> 5, lane = tid & 31;
    const int wr = w / WCOLS, wc = w % WCOLS;
    const int gid = lane >> 2, tig = lane & 3;

    uint32_t sAu = (uint32_t)__cvta_generic_to_shared(sA);
    uint32_t sBu = (uint32_t)__cvta_generic_to_shared(sB);

    float acc[MT][NT][4];
#pragma unroll
    for (int mt = 0; mt < MT; mt++)
#pragma unroll
        for (int nt = 0; nt < NT; nt++)
#pragma unroll
            for (int i = 0; i < 4; i++) acc[mt][nt][i] = 0.f;

    const int nChunks = K3 / BK;

    auto issue = [&](int buf, int k0) {
#pragma unroll
        for (int i = 0; i < 4; i++) {
            const int idx = i * 256 + tid;
            const int r = idx >> 3, kc = (idx & 7) * 8;
            cpa16(sAu + (uint32_t)(((buf * 128 + r) * LDS + kc) * 2),
                  A + (long)(row0 + r) * lda + k0 + kc);
        }
#pragma unroll
        for (int i = 0; i < BITERS; i++) {
            const int idx = i * 256 + tid;
            const int r = idx >> 3, kc = (idx & 7) * 8;
            cpa16(sBu + (uint32_t)(((buf * TN + r) * LDS + kc) * 2),
                  B + (long)(col0 + r) * ldb + k0 + kc);
        }
        asm volatile("cp.async.commit_group;");
    };

    issue(0, 0);
    for (int c = 0; c < nChunks; c++) {
        const int buf = c & 1;
        __syncthreads();                 // all reads of (1-buf) from previous iter done
        if (c + 1 < nChunks) {
            issue(1 - buf, (c + 1) * BK);
            asm volatile("cp.async.wait_group 1;");
        } else {
            asm volatile("cp.async.wait_group 0;");
        }
        __syncthreads();

        const __nv_bfloat16* bA = sA + buf * 128 * LDS;
        const __nv_bfloat16* bB = sB + buf * TN * LDS;
#pragma unroll
        for (int kk = 0; kk < BK; kk += 16) {
            uint32_t af[MT][4], bfr[NT][2];
#pragma unroll
            for (int mt = 0; mt < MT; mt++) {
                const int r = wr * WM + mt * 16 + gid;
                af[mt][0] = *reinterpret_cast<const uint32_t*>(&bA[(r) * LDS + kk + tig * 2]);
                af[mt][1] = *reinterpret_cast<const uint32_t*>(&bA[(r + 8) * LDS + kk + tig * 2]);
                af[mt][2] = *reinterpret_cast<const uint32_t*>(&bA[(r) * LDS + kk + tig * 2 + 8]);
                af[mt][3] = *reinterpret_cast<const uint32_t*>(&bA[(r + 8) * LDS + kk + tig * 2 + 8]);
            }
#pragma unroll
            for (int nt = 0; nt < NT; nt++) {
                const int cidx = wc * WN + nt * 8 + gid;
                bfr[nt][0] = *reinterpret_cast<const uint32_t*>(&bB[cidx * LDS + kk + tig * 2]);
                bfr[nt][1] = *reinterpret_cast<const uint32_t*>(&bB[cidx * LDS + kk + tig * 2 + 8]);
            }
#pragma unroll
            for (int mt = 0; mt < MT; mt++)
#pragma unroll
                for (int nt = 0; nt < NT; nt++) {
                    asm volatile(
                        "mma.sync.aligned.m16n8k16.row.col.f32.bf16.bf16.f32 "
                        "{%0,%1,%2,%3}, {%4,%5,%6,%7}, {%8,%9}, {%0,%1,%2,%3};"
                        : "+f"(acc[mt][nt][0]), "+f"(acc[mt][nt][1]),
                          "+f"(acc[mt][nt][2]), "+f"(acc[mt][nt][3])
                        : "r"(af[mt][0]), "r"(af[mt][1]), "r"(af[mt][2]), "r"(af[mt][3]),
                          "r"(bfr[nt][0]), "r"(bfr[nt][1]));
                }
        }
    }

    // epilogue
#pragma unroll
    for (int mt = 0; mt < MT; mt++) {
#pragma unroll
        for (int nt = 0; nt < NT; nt++) {
            const int rloc = wr * WM + mt * 16 + gid;
            const int cloc = wc * WN + nt * 8 + tig * 2;
            const int cg = col0 + cloc;
            float b0 = bias ? bias[cg] : 0.f;
            float b1 = bias ? bias[cg + 1] : 0.f;
#pragma unroll
            for (int half = 0; half < 2; half++) {
                const int rg = row0 + rloc + half * 8;
                float v0 = acc[mt][nt][half * 2 + 0] * scale + b0;
                float v1 = acc[mt][nt][half * 2 + 1] * scale + b1;
                if (act == 1) { v0 = fmaxf(v0, 0.f); v1 = fmaxf(v1, 0.f); }
                else if (act == 2) {
                    v0 = (v0 > 0.f) ? v0 : expm1f(v0);
                    v1 = (v1 > 0.f) ? v1 : expm1f(v1);
                }
                *reinterpret_cast<float2*>(&C[(long)rg * ldc + cg]) = make_float2(v0, v1);
                if (C3) {
                    __nv_bfloat16 h0 = __float2bfloat16(v0);
                    __nv_bfloat16 l0 = __float2bfloat16(v0 - __bfloat162float(h0));
                    __nv_bfloat16 h1 = __float2bfloat16(v1);
                    __nv_bfloat16 l1 = __float2bfloat16(v1 - __bfloat162float(h1));
                    long base = (long)rg * ldc3 + cg;
                    *reinterpret_cast<__nv_bfloat162*>(&C3[base]) = __nv_bfloat162(h0, h1);
                    *reinterpret_cast<__nv_bfloat162*>(&C3[base + seg3]) = __nv_bfloat162(l0, l1);
                    *reinterpret_cast<__nv_bfloat162*>(&C3[base + 2 * seg3]) = __nv_bfloat162(h0, h1);
                }
            }
        }
    }
}

// ---------------- elementwise kernels ----------------

__global__ void embed_kernel(const int* __restrict__ node, const float* __restrict__ embed,
                             float* __restrict__ x, __nv_bfloat16* __restrict__ x3)
{
    const int row = blockIdx.x;
    const int d = threadIdx.x;
    const float v = embed[(long)node[row] * CD + d];
    x[(long)row * CD + d] = v;
    __nv_bfloat16 h0, h1, h2;
    bf_split_A(v, h0, h1, h2);
    x3[(long)row * 768 + d] = h0;
    x3[(long)row * 768 + 256 + d] = h1;
    x3[(long)row * 768 + 512 + d] = h2;
}

// in [R, C] (row stride irs) -> out [C, 3R] bf16 B-pattern [hi|hi|lo]
__global__ void tsplitB(const float* __restrict__ in, __nv_bfloat16* __restrict__ out,
                        int irs, int R, long sIn1, long sIn2, int divIn, long sOut)
{
    __shared__ float tile[128][33];
    const long z = blockIdx.z;
    in  += (z / divIn) * sIn1 + (z % divIn) * sIn2;
    out += z * sOut;
    const int r0 = blockIdx.x * 128, c0 = blockIdx.y * 32;
    for (int i = threadIdx.x; i < 128 * 32; i += 256) {
        int rr = i >> 5, cc = i & 31;
        tile[rr][cc] = in[(long)(r0 + rr) * irs + c0 + cc];
    }
    __syncthreads();
    for (int i = threadIdx.x; i < 32 * 128; i += 256) {
        int cc = i >> 7, rr = i & 127;
        float v = tile[rr][cc];
        __nv_bfloat16 hi = __float2bfloat16(v);
        __nv_bfloat16 lo = __float2bfloat16(v - __bfloat162float(hi));
        long ob = (long)(c0 + cc) * (3L * R) + (r0 + rr);
        out[ob] = hi; out[ob + R] = hi; out[ob + 2L * R] = lo;
    }
}

// qkv [8192,768]: q at col 0, k at col 256 -> per-(b,h) q3 (A-pat) / k3 (B-pat), padded to 128
__global__ void qk_split(const float* __restrict__ qkv,
                         __nv_bfloat16* __restrict__ q3, __nv_bfloat16* __restrict__ k3)
{
    const int row = blockIdx.x;
    const int b = row >> 9, i = row & 511;
    const int d = threadIdx.x;
    const int h = d >> 5, dd = d & 31;
    const long base = ((long)(b * CH + h) * CN + i) * 128;
    const __nv_bfloat16 zero = __float2bfloat16(0.f);
    float qv = qkv[(long)row * 768 + d];
    float kv = qkv[(long)row * 768 + 256 + d];
    __nv_bfloat16 qh = __float2bfloat16(qv);
    __nv_bfloat16 ql = __float2bfloat16(qv - __bfloat162float(qh));
    __nv_bfloat16 kh = __float2bfloat16(kv);
    __nv_bfloat16 kl = __float2bfloat16(kv - __bfloat162float(kh));
    q3[base + dd] = qh;  q3[base + 32 + dd] = ql; q3[base + 64 + dd] = qh; q3[base + 96 + dd] = zero;
    k3[base + dd] = kh;  k3[base + 32 + dd] = kh; k3[base + 64 + dd] = kl; k3[base + 96 + dd] = zero;
}

__global__ void e12_kernel(const float* __restrict__ h, const float* __restrict__ a1,
                           const float* __restrict__ a2, float* __restrict__ e1, float* __restrict__ e2)
{
    const int row = blockIdx.x;
    const int d = threadIdx.x;
    __shared__ float s1[256], s2[256];
    const float hv = h[(long)row * CD + d];
    s1[d] = hv * a1[d];
    s2[d] = hv * a2[d];
    __syncthreads();
    for (int off = 128; off > 0; off >>= 1) {
        if (d < off) { s1[d] += s1[d + off]; s2[d] += s2[d + off]; }
        __syncthreads();
    }
    if (d == 0) { e1[row] = s1[0]; e2[row] = s2[0]; }
}

__global__ void gat_softmax_kernel(const float* __restrict__ e1, const float* __restrict__ e2,
                                   const int* __restrict__ edge, __nv_bfloat16* __restrict__ al3)
{
    const int row = blockIdx.x;
    const int b = row / CN;
    const int t = threadIdx.x;
    __shared__ float red[256];
    const float ei = e1[row];
    float vals[2];
#pragma unroll
    for (int p = 0; p < 2; p++) {
        const int j = t + p * 256;
        float e = ei + e2[b * CN + j];
        e = (e >= 0.f) ? e : 0.2f * e;
        vals[p] = (edge[(long)row * CN + j] > 0) ? e : NEG_INF_F;
    }
    red[t] = fmaxf(vals[0], vals[1]);
    __syncthreads();
    for (int off = 128; off > 0; off >>= 1) { if (t < off) red[t] = fmaxf(red[t], red[t + off]); __syncthreads(); }
    const float m = red[0];
    __syncthreads();
    float ex[2] = {__expf(vals[0] - m), __expf(vals[1] - m)};
    red[t] = ex[0] + ex[1];
    __syncthreads();
    for (int off = 128; off > 0; off >>= 1) { if (t < off) red[t] += red[t + off]; __syncthreads(); }
    const float inv = 1.f / red[0];
    const long b3 = (long)row * 1536;
#pragma unroll
    for (int p = 0; p < 2; p++) {
        const int j = t + p * 256;
        __nv_bfloat16 h0, h1, h2;
        bf_split_A(ex[p] * inv, h0, h1, h2);
        al3[b3 + j] = h0; al3[b3 + 512 + j] = h1; al3[b3 + 1024 + j] = h2;
    }
}

__global__ void mha_softmax_kernel(float* __restrict__ s, const int* __restrict__ mask,
                                   __nv_bfloat16* __restrict__ at3)
{
    const int r = blockIdx.x;
    const int b = r / (CH * CN);
    const int t = threadIdx.x;
    __shared__ float red[256];
    float* srow = s + (long)r * CN;
    float vals[2];
#pragma unroll
    for (int p = 0; p < 2; p++) {
        const int j = t + p * 256;
        vals[p] = srow[j] + (float)mask[b * CN + j] * NEG_INF_F;
    }
    red[t] = fmaxf(vals[0], vals[1]);
    __syncthreads();
    for (int off = 128; off > 0; off >>= 1) { if (t < off) red[t] = fmaxf(red[t], red[t + off]); __syncthreads(); }
    const float m = red[0];
    __syncthreads();
    float ex[2] = {__expf(vals[0] - m), __expf(vals[1] - m)};
    red[t] = ex[0] + ex[1];
    __syncthreads();
    for (int off = 128; off > 0; off >>= 1) { if (t < off) red[t] += red[t + off]; __syncthreads(); }
    const float inv = 1.f / red[0];
    const long b3 = (long)r * 1536;
#pragma unroll
    for (int p = 0; p < 2; p++) {
        const int j = t + p * 256;
        const float pr = ex[p] * inv;
        srow[j] = pr;
        __nv_bfloat16 h0, h1, h2;
        bf_split_A(pr, h0, h1, h2);
        at3[b3 + j] = h0; at3[b3 + 512 + j] = h1; at3[b3 + 1024 + j] = h2;
    }
}

__global__ void scale_pe_kernel(float* __restrict__ x, __nv_bfloat16* __restrict__ x3)
{
    const int row = blockIdx.x;
    const int n = row % CN;
    const int d = threadIdx.x;
    const float expo = (2.0f * (float)(d >> 1)) / (float)CD;
    const float angle = (float)n * powf(10000.0f, -expo);
    const float pe = (d & 1) ? cosf(angle) : sinf(angle);
    const long idx = (long)row * CD + d;
    const float v = x[idx] * 16.0f + pe;
    x[idx] = v;
    __nv_bfloat16 h0, h1, h2;
    bf_split_A(v, h0, h1, h2);
    x3[(long)row * 768 + d] = h0;
    x3[(long)row * 768 + 256 + d] = h1;
    x3[(long)row * 768 + 512 + d] = h2;
}

__global__ void ln_kernel(const float* __restrict__ x, const float* __restrict__ delta,
                          const float* __restrict__ g, const float* __restrict__ bb,
                          float* __restrict__ out, __nv_bfloat16* __restrict__ x3)
{
    const int row = blockIdx.x;
    const int d = threadIdx.x;
    __shared__ float red[256];
    const long idx = (long)row * CD + d;
    const float v = x[idx] + delta[idx];
    red[d] = v;
    __syncthreads();
    for (int off = 128; off > 0; off >>= 1) { if (d < off) red[d] += red[d + off]; __syncthreads(); }
    const float mu = red[0] * (1.0f / CD);
    __syncthreads();
    const float c = v - mu;
    red[d] = c * c;
    __syncthreads();
    for (int off = 128; off > 0; off >>= 1) { if (d < off) red[d] += red[d + off]; __syncthreads(); }
    const float var = red[0] * (1.0f / CD);
    const float r = c * rsqrtf(var + 1e-6f) * g[d] + bb[d];
    out[idx] = r;
    __nv_bfloat16 h0, h1, h2;
    bf_split_A(r, h0, h1, h2);
    x3[(long)row * 768 + d] = h0;
    x3[(long)row * 768 + 256 + d] = h1;
    x3[(long)row * 768 + 512 + d] = h2;
}

__global__ void copy_kernel(const float* __restrict__ src, float* __restrict__ dst, long n)
{
    const long i = (long)blockIdx.x * blockDim.x + threadIdx.x;
    if (i < n) dst[i] = src[i];
}

// ---------------- host ----------------
struct G3 { __nv_bfloat16* p; long s1; long s2; int ld; int seg; };

static void launch_gemm(const __nv_bfloat16* A, const __nv_bfloat16* B, const float* bias, float* C,
                        int M, int N, int K3, int lda, int ldb, int ldc,
                        long sA, long sB, long sC1, long sC2, int divC,
                        float scale, int act, int batch, int tileN, G3 g3)
{
    if (tileN == 128) {
        dim3 g(N / 128, M / 128, batch);
        size_t sm = (2 * 128 + 2 * 128) * 72 * 2;
        gemm_mma<128, 64, 32><<<g, 256, sm>>>(A, B, bias, C, lda, ldb, ldc, K3,
            sA, sB, sC1, sC2, divC, scale, act, g3.p, g3.s1, g3.s2, g3.ld, g3.seg);
    } else if (tileN == 64) {
        dim3 g(N / 64, M / 128, batch);
        size_t sm = (2 * 128 + 2 * 64) * 72 * 2;
        gemm_mma<64, 32, 32><<<g, 256, sm>>>(A, B, bias, C, lda, ldb, ldc, K3,
            sA, sB, sC1, sC2, divC, scale, act, g3.p, g3.s1, g3.s2, g3.ld, g3.seg);
    } else {
        dim3 g(N / 32, M / 128, batch);
        size_t sm = (2 * 128 + 2 * 32) * 72 * 2;
        gemm_mma<32, 32, 16><<<g, 256, sm>>>(A, B, bias, C, lda, ldb, ldc, K3,
            sA, sB, sC1, sC2, divC, scale, act, g3.p, g3.s1, g3.s2, g3.ld, g3.seg);
    }
}

extern "C" void kernel_launch(void* const* d_in, const int* in_sizes, int n_in,
                              void* d_out, int out_size)
{
    const int*   node  = (const int*)  d_in[0];
    const int*   edge  = (const int*)  d_in[1];
    const int*   mask  = (const int*)  d_in[2];
    const float* embed = (const float*)d_in[4];
    const float* Wg    = (const float*)d_in[5];
    const float* a1    = (const float*)d_in[6];
    const float* a2    = (const float*)d_in[7];
    const float* Wq    = (const float*)d_in[8];
    const float* bq    = (const float*)d_in[9];
    const float* Wk    = (const float*)d_in[10];
    const float* bk    = (const float*)d_in[11];
    const float* Wv    = (const float*)d_in[12];
    const float* bv    = (const float*)d_in[13];
    const float* Wo    = (const float*)d_in[14];
    const float* bo    = (const float*)d_in[15];
    const float* W1    = (const float*)d_in[16];
    const float* b1    = (const float*)d_in[17];
    const float* W2    = (const float*)d_in[18];
    const float* b2    = (const float*)d_in[19];
    const float* ln1g  = (const float*)d_in[20];
    const float* ln1b  = (const float*)d_in[21];
    const float* ln2g  = (const float*)d_in[22];
    const float* ln2b  = (const float*)d_in[23];

    cudaFuncSetAttribute((const void*)gemm_mma<128,64,32>, cudaFuncAttributeMaxDynamicSharedMemorySize, 75000);
    cudaFuncSetAttribute((const void*)gemm_mma<64,32,32>,  cudaFuncAttributeMaxDynamicSharedMemorySize, 60000);
    cudaFuncSetAttribute((const void*)gemm_mma<32,32,16>,  cudaFuncAttributeMaxDynamicSharedMemorySize, 50000);

    float *x, *h, *qkv, *t, *ff, *e1, *e2, *bias3;
    __nv_bfloat16 *x3, *o3, *ff3, *h3t, *al3, *at3, *q3, *k3, *v3t, *wb, *wg3;
    cudaGetSymbolAddress((void**)&x, g_x);     cudaGetSymbolAddress((void**)&h, g_h);
    cudaGetSymbolAddress((void**)&qkv, g_qkv); cudaGetSymbolAddress((void**)&t, g_t);
    cudaGetSymbolAddress((void**)&ff, g_ff);
    cudaGetSymbolAddress((void**)&e1, g_e1);   cudaGetSymbolAddress((void**)&e2, g_e2);
    cudaGetSymbolAddress((void**)&bias3, g_bias);
    cudaGetSymbolAddress((void**)&x3, g_x3);   cudaGetSymbolAddress((void**)&o3, g_o3);
    cudaGetSymbolAddress((void**)&ff3, g_ff3); cudaGetSymbolAddress((void**)&h3t, g_h3t);
    cudaGetSymbolAddress((void**)&al3, g_al3); cudaGetSymbolAddress((void**)&at3, g_at3);
    cudaGetSymbolAddress((void**)&q3, g_q3);   cudaGetSymbolAddress((void**)&k3, g_k3);
    cudaGetSymbolAddress((void**)&v3t, g_v3t); cudaGetSymbolAddress((void**)&wb, g_wb);
    cudaGetSymbolAddress((void**)&wg3, g_wg3);

    float* out_x    = (float*)d_out;
    float* out_attn = (float*)d_out + (long)CB * CN * CD;

    const int M = CB * CN;
    const long ND = (long)CN * CD;
    const float inv_sqrt_dh = 0.17677669529663687f;
    const G3 no3 = {nullptr, 0, 0, 0, 0};

    embed_kernel<<<M, CD>>>(node, embed, x, x3);
    tsplitB<<<dim3(2, 8, 1), 256>>>(Wg, wg3, CD, CD, 0, 0, 1, 0);

    for (int hop = 0; hop < 2; hop++) {
        launch_gemm(x3, wg3, nullptr, h, M, CD, 768, 768, 768, CD,
                    0, 0, 0, 0, 1, 1.f, 0, 1, 64, no3);
        tsplitB<<<dim3(4, 8, CB), 256>>>(h, h3t, CD, CN, ND, 0, 1, (long)CD * 1536);
        e12_kernel<<<M, CD>>>(h, a1, a2, e1, e2);
        gat_softmax_kernel<<<M, 256>>>(e1, e2, edge, al3);
        // x = elu(alpha@h), also emit x3 for next consumer
        G3 gx3 = {x3, (long)CN * 768, 0, 768, 256};
        launch_gemm(al3, h3t, nullptr, x, CN, CD, 1536, 1536, 1536, CD,
                    (long)CN * 1536, (long)CD * 1536, ND, 0, 1, 1.f, 2, CB, 64, gx3);
    }

    scale_pe_kernel<<<M, CD>>>(x, x3);

    for (int l = 0; l < CL; l++) {
        const long wOff = (long)l * CD * CD;
        // pack Wq|Wk|Wv (B-pattern splits) and biases
        tsplitB<<<dim3(2, 8, 1), 256>>>(Wq + wOff, wb, CD, CD, 0, 0, 1, 0);
        tsplitB<<<dim3(2, 8, 1), 256>>>(Wk + wOff, wb + 256 * 768, CD, CD, 0, 0, 1, 0);
        tsplitB<<<dim3(2, 8, 1), 256>>>(Wv + wOff, wb + 512 * 768, CD, CD, 0, 0, 1, 0);
        cudaMemcpyAsync(bias3,       bq + l * CD, CD * 4, cudaMemcpyDeviceToDevice, 0);
        cudaMemcpyAsync(bias3 + 256, bk + l * CD, CD * 4, cudaMemcpyDeviceToDevice, 0);
        cudaMemcpyAsync(bias3 + 512, bv + l * CD, CD * 4, cudaMemcpyDeviceToDevice, 0);

        // fused QKV: [8192,768] = x3 @ wb^T
        launch_gemm(x3, wb, bias3, qkv, M, 768, 768, 768, 768, 768,
                    0, 0, 0, 0, 1, 1.f, 0, 1, 128, no3);

        qk_split<<<M, 256>>>(qkv, q3, k3);
        tsplitB<<<dim3(4, 1, CB * CH), 256>>>(qkv + 512, v3t, 768, CN,
                                              (long)CN * 768, 32, CH, 32L * 1536);

        // scores = q@k^T / sqrt(dh) -> out_attn
        launch_gemm(q3, k3, nullptr, out_attn, CN, CN, 128, 128, 128, CN,
                    (long)CN * 128, (long)CN * 128, (long)CN * CN, 0, 1,
                    inv_sqrt_dh, 0, CB * CH, 128, no3);

        mha_softmax_kernel<<<CB * CH * CN, 256>>>(out_attn, mask, at3);

        // o = attn@v (per head), emit o3 directly
        G3 go3 = {o3, (long)CN * 768, 32, 768, 256};
        launch_gemm(at3, v3t, nullptr, t /*o fp32 unused later; reuse t*/, CN, 32, 1536, 1536, 1536, CD,
                    (long)CN * 1536, 32L * 1536, ND, 32, CH, 1.f, 0, CB * CH, 32, go3);

        // t = o@Wo + bo ; x = LN(x+t)
        tsplitB<<<dim3(2, 8, 1), 256>>>(Wo + wOff, wb, CD, CD, 0, 0, 1, 0);
        launch_gemm(o3, wb, bo + l * CD, t, M, CD, 768, 768, 768, CD,
                    0, 0, 0, 0, 1, 1.f, 0, 1, 64, no3);
        ln_kernel<<<M, CD>>>(x, t, ln1g + l * CD, ln1b + l * CD, x, x3);

        // FFN
        tsplitB<<<dim3(2, 32, 1), 256>>>(W1 + (long)l * CD * CDFF, wb, CDFF, CD, 0, 0, 1, 0);
        G3 gff3 = {ff3, 0, 0, 3072, 1024};
        launch_gemm(x3, wb, b1 + l * CDFF, ff, M, CDFF, 768, 768, 768, CDFF,
                    0, 0, 0, 0, 1, 1.f, 1, 1, 128, gff3);
        tsplitB<<<dim3(8, 8, 1), 256>>>(W2 + (long)l * CDFF * CD, wb, CD, CDFF, 0, 0, 1, 0);
        launch_gemm(ff3, wb, b2 + l * CD, t, M, CD, 3072, 3072, 3072, CD,
                    0, 0, 0, 0, 1, 1.f, 0, 1, 64, no3);
        ln_kernel<<<M, CD>>>(x, t, ln2g + l * CD, ln2b + l * CD, x, x3);
    }

    const long xcount = (long)CB * CN * CD;
    copy_kernel<<<(int)((xcount + 255) / 256), 256>>>(x, out_x, xcount);
}